// round 5
// baseline (speedup 1.0000x reference)
#include <cuda_runtime.h>
#include <cstdint>

#define W   256
#define NB  128     // n = hn*bs
#define C   128
#define NE  8       // heads
#define HD  16
#define D2  511     // 2W-1
#define ROWS (W*NB) // 32768
#define HN  64

// ---------------- scratch (device globals; no allocation) ----------------
__device__ float g_fl[ROWS*C];
__device__ float g_fr[ROWS*C];
__device__ float g_fl2[ROWS*C];
__device__ float g_fr2[ROWS*C];
__device__ float g_q[ROWS*C];
__device__ float g_kv[ROWS*2*C];
__device__ float g_vo[ROWS*C];
__device__ float g_qr[D2*C];
__device__ float g_kr[D2*C];
__device__ float g_attn[(size_t)NB*NE*W*W];   // 268 MB

// fast exp on the FMA pipe (MUFU rt=8/SMSP on B300 makes __expf the softmax bottleneck)
// x <= 0 expected; clamp at -80 keeps the bit-splice in normal range.
__device__ __forceinline__ float fexp(float x) {
    float y = fmaxf(x, -80.0f) * 1.44269504f;
    float z = y + 12582912.0f;                    // round-to-nearest int (magic)
    int   n = __float_as_int(z) - 0x4B400000;
    float f = y - (z - 12582912.0f);              // f in [-0.5, 0.5]
    float p =              1.8775767e-3f;
    p = fmaf(p, f, 8.9893397e-3f);
    p = fmaf(p, f, 5.5826318e-2f);
    p = fmaf(p, f, 2.4015361e-1f);
    p = fmaf(p, f, 6.9315308e-1f);
    p = fmaf(p, f, 9.9999994e-1f);
    return __int_as_float(__float_as_int(p) + (n << 23));
}

// ---------------- reorder in: (bs,c,hn,w) -> X[i][j][cc], j=h*2+b ----------------
__global__ void k_reorder_in(const float* __restrict__ in, float* __restrict__ out) {
    __shared__ float sm[32][33];
    int itile = blockIdx.x*32, cctile = blockIdx.y*32, hb = blockIdx.z;
    int h = hb >> 1, b = hb & 1, j = h*2 + b;
    int tx = threadIdx.x, ty = threadIdx.y;
    #pragma unroll
    for (int r = 0; r < 32; r += 8) {
        int cc = cctile + r + ty;
        sm[r+ty][tx] = in[ ((b*C + cc)*HN + h)*W + itile + tx ];
    }
    __syncthreads();
    #pragma unroll
    for (int r = 0; r < 32; r += 8) {
        int i = itile + r + ty;
        out[ (i*NB + j)*C + cctile + tx ] = sm[tx][r+ty];
    }
}

// ---------------- reorder out: X[i][j][cc] -> (bs,c,hn,w) ----------------
__global__ void k_reorder_out(const float* __restrict__ X, float* __restrict__ out) {
    __shared__ float sm[32][33];
    int itile = blockIdx.x*32, cctile = blockIdx.y*32, hb = blockIdx.z;
    int h = hb >> 1, b = hb & 1, j = h*2 + b;
    int tx = threadIdx.x, ty = threadIdx.y;
    #pragma unroll
    for (int r = 0; r < 32; r += 8) {
        int i = itile + r + ty;
        sm[r+ty][tx] = X[ (i*NB + j)*C + cctile + tx ];
    }
    __syncthreads();
    #pragma unroll
    for (int r = 0; r < 32; r += 8) {
        int cc = cctile + r + ty;
        out[ ((b*C + cc)*HN + h)*W + itile + tx ] = sm[tx][r+ty];
    }
}

// ---------------- layernorm over last dim (C=128), one row per block ----------------
__global__ void k_layernorm(const float* __restrict__ X, float* __restrict__ Y,
                            const float* __restrict__ g, const float* __restrict__ b) {
    int row = blockIdx.x;
    int t = threadIdx.x;          // 128
    float x = X[row*C + t];
    __shared__ float red[4];
    float s = x;
    #pragma unroll
    for (int o = 16; o; o >>= 1) s += __shfl_xor_sync(0xffffffffu, s, o);
    if ((t & 31) == 0) red[t >> 5] = s;
    __syncthreads();
    float mean = (red[0]+red[1]+red[2]+red[3]) * (1.0f/C);
    float d = x - mean;
    float s2 = d*d;
    #pragma unroll
    for (int o = 16; o; o >>= 1) s2 += __shfl_xor_sync(0xffffffffu, s2, o);
    __syncthreads();
    if ((t & 31) == 0) red[t >> 5] = s2;
    __syncthreads();
    float var = (red[0]+red[1]+red[2]+red[3]) * (1.0f/C);
    Y[row*C + t] = d * rsqrtf(var + 1e-5f) * g[t] + b[t];
}

// ---------------- SGEMM v2: tile 64(M)x128(N), K chunked by 32, LDS.128 fragments ----
__global__ __launch_bounds__(256, 4)
void k_gemm(const float* __restrict__ A, const float* __restrict__ Wr,
            const float* __restrict__ bias, const float* __restrict__ res,
            float* __restrict__ Cout, int M, float scale, int ldc) {
    __shared__ float As[32*68];    // [k][m]
    __shared__ float Bs[32*132];   // [k][n]
    int m0 = blockIdx.x*64, n0 = blockIdx.y*128;
    int tid = threadIdx.x;
    int tx = tid & 15, ty = tid >> 4;
    float acc[4][8] = {};

    for (int kc = 0; kc < 128; kc += 32) {
        __syncthreads();
        #pragma unroll
        for (int rep = 0; rep < 2; rep++) {
            int f4 = tid + rep*256;
            int m = f4 >> 3, k4 = f4 & 7;
            int gm = m0 + m;
            float4 v = (gm < M) ? *(const float4*)&A[(size_t)gm*128 + kc + k4*4]
                                : make_float4(0.f,0.f,0.f,0.f);
            As[(4*k4+0)*68 + m] = v.x;
            As[(4*k4+1)*68 + m] = v.y;
            As[(4*k4+2)*68 + m] = v.z;
            As[(4*k4+3)*68 + m] = v.w;
        }
        #pragma unroll
        for (int rep = 0; rep < 4; rep++) {
            int f4 = tid + rep*256;
            int n = f4 >> 3, k4 = f4 & 7;
            float4 v = *(const float4*)&Wr[(size_t)(n0+n)*128 + kc + k4*4];
            Bs[(4*k4+0)*132 + n] = v.x;
            Bs[(4*k4+1)*132 + n] = v.y;
            Bs[(4*k4+2)*132 + n] = v.z;
            Bs[(4*k4+3)*132 + n] = v.w;
        }
        __syncthreads();
        #pragma unroll
        for (int kk = 0; kk < 32; kk++) {
            float4 a  = *(float4*)&As[kk*68 + 4*ty];
            float4 b0 = *(float4*)&Bs[kk*132 + 4*tx];
            float4 b1 = *(float4*)&Bs[kk*132 + 64 + 4*tx];
            float av[4] = {a.x, a.y, a.z, a.w};
            float bv[8] = {b0.x, b0.y, b0.z, b0.w, b1.x, b1.y, b1.z, b1.w};
            #pragma unroll
            for (int r = 0; r < 4; r++)
                #pragma unroll
                for (int c = 0; c < 8; c++) acc[r][c] += av[r]*bv[c];
        }
    }

    float4 bi0 = *(const float4*)&bias[n0 + 4*tx];
    float4 bi1 = *(const float4*)&bias[n0 + 64 + 4*tx];
    float bb[8] = {bi0.x, bi0.y, bi0.z, bi0.w, bi1.x, bi1.y, bi1.z, bi1.w};
    #pragma unroll
    for (int r = 0; r < 4; r++) {
        int gm = m0 + 4*ty + r;
        if (gm >= M) continue;
        float o[8];
        #pragma unroll
        for (int c = 0; c < 8; c++) o[c] = scale * (acc[r][c] + bb[c]);
        size_t base = (size_t)gm*ldc + n0;
        if (res) {
            float4 r0 = *(const float4*)&res[base + 4*tx];
            float4 r1 = *(const float4*)&res[base + 64 + 4*tx];
            o[0]+=r0.x; o[1]+=r0.y; o[2]+=r0.z; o[3]+=r0.w;
            o[4]+=r1.x; o[5]+=r1.y; o[6]+=r1.z; o[7]+=r1.w;
        }
        *(float4*)&Cout[base + 4*tx]      = make_float4(o[0],o[1],o[2],o[3]);
        *(float4*)&Cout[base + 64 + 4*tx] = make_float4(o[4],o[5],o[6],o[7]);
    }
}

// ---------------- scores: attn[n,e,i,v] = q·k + q·kr[d] + qr[d]·k, d = 255+sgn*(i-v) ----
__global__ __launch_bounds__(256, 3)
void k_scores(const float* __restrict__ q, const float* __restrict__ kv,
              const float* __restrict__ qr, const float* __restrict__ kr,
              float* __restrict__ attn, int sgn) {
    __shared__ float Qs[64*17];
    __shared__ float Ks[128*17];
    __shared__ float QRs[192*17];
    __shared__ float KRs[192*17];
    int i0 = (blockIdx.x >> 1) * 64;
    int v0 = (blockIdx.x & 1) * 128;
    int e = blockIdx.y, n = blockIdx.z;
    int tid = threadIdx.x;
    int dmin = (sgn > 0) ? (128 + i0 - v0) : (192 - i0 + v0);
    for (int idx = tid; idx < 64*16; idx += 256) {
        int r = idx >> 4, cc = idx & 15;
        Qs[r*17+cc] = q[(size_t)((i0+r)*NB + n)*C + e*16 + cc];
    }
    for (int idx = tid; idx < 128*16; idx += 256) {
        int r = idx >> 4, cc = idx & 15;
        Ks[r*17+cc] = kv[(size_t)((v0+r)*NB + n)*(2*C) + e*16 + cc];
    }
    for (int idx = tid; idx < 192*16; idx += 256) {
        int r = idx >> 4, cc = idx & 15;
        QRs[r*17+cc] = qr[(dmin+r)*C + e*16 + cc];
        KRs[r*17+cc] = kr[(dmin+r)*C + e*16 + cc];
    }
    __syncthreads();
    int ty = tid & 15, tx = tid >> 4;
    int ib = ty*4, vb = tx*8;
    int dbase = (sgn > 0) ? (127 + ib - vb) : (63 - ib + vb);
    int doff[11];
    #pragma unroll
    for (int k = 0; k < 11; k++) doff[k] = (dbase + sgn*(k - 7))*17;
    float acc[4][8] = {};
    #pragma unroll 2
    for (int cc = 0; cc < 16; cc++) {
        float qa[4], ka[8], qrl[11], krl[11];
        #pragma unroll
        for (int r = 0; r < 4; r++) qa[r] = Qs[(ib+r)*17 + cc];
        #pragma unroll
        for (int r = 0; r < 8; r++) ka[r] = Ks[(vb+r)*17 + cc];
        #pragma unroll
        for (int k = 0; k < 11; k++) { qrl[k] = QRs[doff[k] + cc]; krl[k] = KRs[doff[k] + cc]; }
        #pragma unroll
        for (int ri = 0; ri < 4; ri++)
            #pragma unroll
            for (int rv = 0; rv < 8; rv++) {
                int k = ri - rv + 7;
                acc[ri][rv] += qa[ri]*(ka[rv] + krl[k]) + qrl[k]*ka[rv];
            }
    }
    #pragma unroll
    for (int ri = 0; ri < 4; ri++) {
        int i = i0 + ib + ri;
        float4* dst = (float4*)&attn[ ((size_t)(n*NE + e)*W + i)*W + v0 + vb ];
        dst[0] = make_float4(acc[ri][0], acc[ri][1], acc[ri][2], acc[ri][3]);
        dst[1] = make_float4(acc[ri][4], acc[ri][5], acc[ri][6], acc[ri][7]);
    }
}

// ---------------- softmax over v for all 8 heads of one (n,i); optional rawsum output ----
__global__ void k_softmax(float* __restrict__ attn, float* __restrict__ rawout) {
    int i = blockIdx.x, n = blockIdx.y;
    int v = threadIdx.x;   // 256
    float val[NE];
    #pragma unroll
    for (int e = 0; e < NE; e++) val[e] = attn[ ((size_t)(n*NE + e)*W + i)*W + v ];
    if (rawout) {
        float s = 0.f;
        #pragma unroll
        for (int e = 0; e < NE; e++) s += val[e];
        int b = n & 1, h = n >> 1;
        rawout[ ((size_t)(b*HN + h)*W + i)*W + v ] = s;
    }
    __shared__ float red[NE][8];
    __shared__ float bc[NE];
    int wid = v >> 5, lane = v & 31;
    float m[NE];
    #pragma unroll
    for (int e = 0; e < NE; e++) {
        m[e] = val[e];
        #pragma unroll
        for (int o = 16; o; o >>= 1) m[e] = fmaxf(m[e], __shfl_xor_sync(0xffffffffu, m[e], o));
    }
    #pragma unroll
    for (int e = 0; e < NE; e++) if (lane == e) red[e][wid] = m[e];
    __syncthreads();
    if (v < NE) {
        float mm = red[v][0];
        #pragma unroll
        for (int wI = 1; wI < 8; wI++) mm = fmaxf(mm, red[v][wI]);
        bc[v] = mm;
    }
    __syncthreads();
    float se[NE];
    #pragma unroll
    for (int e = 0; e < NE; e++) {
        val[e] = fexp(val[e] - bc[e]);
        se[e] = val[e];
        #pragma unroll
        for (int o = 16; o; o >>= 1) se[e] += __shfl_xor_sync(0xffffffffu, se[e], o);
    }
    __syncthreads();
    #pragma unroll
    for (int e = 0; e < NE; e++) if (lane == e) red[e][wid] = se[e];
    __syncthreads();
    if (v < NE) {
        float ss = 0.f;
        #pragma unroll
        for (int wI = 0; wI < 8; wI++) ss += red[v][wI];
        bc[v] = 1.0f / ss;
    }
    __syncthreads();
    #pragma unroll
    for (int e = 0; e < NE; e++) attn[ ((size_t)(n*NE + e)*W + i)*W + v ] = val[e] * bc[e];
}

// ---------------- AV: vo[i,n,e*16+cc] = sum_v P[n,e,i,v] * V[v,n,e*16+cc] ----------------
__global__ void k_av(const float* __restrict__ attn, const float* __restrict__ kv,
                     float* __restrict__ vo) {
    __shared__ float Ps[256][33];
    __shared__ float Vs[32][17];
    int e = blockIdx.x, n = blockIdx.y;
    int t = threadIdx.x;
    float acc[2][16] = {};
    const float* P = attn + (size_t)(n*NE + e)*W*W;
    for (int v0 = 0; v0 < W; v0 += 32) {
        __syncthreads();
        #pragma unroll
        for (int k = 0; k < 64; k++) {
            int idx = t + k*128;
            int ii = idx >> 5, vv = idx & 31;
            Ps[ii][vv] = P[(size_t)ii*W + v0 + vv];
        }
        #pragma unroll
        for (int k = 0; k < 4; k++) {
            int idx = t + k*128;
            int vv = idx >> 4, cc = idx & 15;
            Vs[vv][cc] = kv[(size_t)((v0+vv)*NB + n)*(2*C) + C + e*16 + cc];
        }
        __syncthreads();
        #pragma unroll 4
        for (int vv = 0; vv < 32; vv++) {
            float p0 = Ps[t][vv], p1 = Ps[t+128][vv];
            #pragma unroll
            for (int cc = 0; cc < 16; cc++) {
                float vx = Vs[vv][cc];
                acc[0][cc] += p0*vx;
                acc[1][cc] += p1*vx;
            }
        }
    }
    #pragma unroll
    for (int r = 0; r < 2; r++) {
        int i = t + r*128;
        float* dst = &vo[(size_t)(i*NB + n)*C + e*16];
        #pragma unroll
        for (int cc = 0; cc < 16; cc++) dst[cc] = acc[r][cc];
    }
}

// ---------------- host ----------------
extern "C" void kernel_launch(void* const* d_in, const int* in_sizes, int n_in,
                              void* d_out, int out_size) {
    const float* feat_left  = (const float*)d_in[0];
    const float* feat_right = (const float*)d_in[1];
    const float* pos        = (const float*)d_in[2];
    // d_in[3] pos_indexes: analytic d = 255 +/- (i-v) used instead
    const float* Wqkv = (const float*)d_in[4];
    const float* bqkv = (const float*)d_in[5];
    const float* Wo   = (const float*)d_in[6];
    const float* bo   = (const float*)d_in[7];
    const float* g1   = (const float*)d_in[8];
    const float* b1   = (const float*)d_in[9];
    const float* g2   = (const float*)d_in[10];
    const float* b2   = (const float*)d_in[11];
    float* out = (float*)d_out;

    float *fl,*fr,*fl2,*fr2,*q,*kv,*vo,*qr,*kr,*attn;
    cudaGetSymbolAddress((void**)&fl,   g_fl);
    cudaGetSymbolAddress((void**)&fr,   g_fr);
    cudaGetSymbolAddress((void**)&fl2,  g_fl2);
    cudaGetSymbolAddress((void**)&fr2,  g_fr2);
    cudaGetSymbolAddress((void**)&q,    g_q);
    cudaGetSymbolAddress((void**)&kv,   g_kv);
    cudaGetSymbolAddress((void**)&vo,   g_vo);
    cudaGetSymbolAddress((void**)&qr,   g_qr);
    cudaGetSymbolAddress((void**)&kr,   g_kr);
    cudaGetSymbolAddress((void**)&attn, g_attn);

    dim3 bt(32, 8);
    dim3 gt(8, 4, 128);

    // to_seq + LN(g1,b1)
    k_reorder_in<<<gt, bt>>>(feat_left,  fl);
    k_reorder_in<<<gt, bt>>>(feat_right, fr);
    k_layernorm<<<ROWS, 128>>>(fl, fl2, g1, b1);
    k_layernorm<<<ROWS, 128>>>(fr, fr2, g1, b1);

    // positional tables: qr = 0.25*(pos@Wq^T+bq), kr = pos@Wk^T+bk
    k_gemm<<<dim3(8,1), 256>>>(pos, Wqkv,           bqkv,     nullptr, qr, D2, 0.25f, 128);
    k_gemm<<<dim3(8,1), 256>>>(pos, Wqkv + 128*128, bqkv+128, nullptr, kr, D2, 1.0f,  128);

    // ---- MHA 1: q from fr2, kv from fl2, flipped pos => d = 255 - (i - v) ----
    k_gemm<<<dim3(512,1), 256>>>(fr2, Wqkv,           bqkv,     nullptr, q,  ROWS, 0.25f, 128);
    k_gemm<<<dim3(512,2), 256>>>(fl2, Wqkv + 128*128, bqkv+128, nullptr, kv, ROWS, 1.0f,  256);
    k_scores<<<dim3(8, NE, NB), 256>>>(q, kv, qr, kr, attn, -1);
    k_softmax<<<dim3(W, NB), 256>>>(attn, nullptr);
    k_av<<<dim3(NE, NB), 128>>>(attn, kv, vo);
    k_gemm<<<dim3(512,1), 256>>>(vo, Wo, bo, fr, fr, ROWS, 1.0f, 128);  // fr += upd_r

    // fr2 <- ln(fr, g2, b2)
    k_layernorm<<<ROWS, 128>>>(fr, fr2, g2, b2);

    // ---- MHA 2: q from fl2, kv from fr2, d = 255 + (i - v), rawsum -> output ----
    k_gemm<<<dim3(512,1), 256>>>(fl2, Wqkv,           bqkv,     nullptr, q,  ROWS, 0.25f, 128);
    k_gemm<<<dim3(512,2), 256>>>(fr2, Wqkv + 128*128, bqkv+128, nullptr, kv, ROWS, 1.0f,  256);
    k_scores<<<dim3(8, NE, NB), 256>>>(q, kv, qr, kr, attn, +1);
    k_softmax<<<dim3(W, NB), 256>>>(attn, out + 8388608);
    k_av<<<dim3(NE, NB), 128>>>(attn, kv, vo);
    k_gemm<<<dim3(512,1), 256>>>(vo, Wo, bo, fl, fl, ROWS, 1.0f, 128);  // fl += upd_l

    // from_seq
    k_reorder_out<<<gt, bt>>>(fl, out);
    k_reorder_out<<<gt, bt>>>(fr, out + 4194304);
}

// round 6
// speedup vs baseline: 1.6077x; 1.6077x over previous
#include <cuda_runtime.h>
#include <cstdint>

#define W   256
#define NB  128     // n = hn*bs
#define C   128
#define NE  8       // heads
#define HD  16
#define D2  511     // 2W-1
#define ROWS (W*NB) // 32768
#define HN  64

// ---------------- scratch (device globals; no allocation) ----------------
__device__ float g_fl[ROWS*C];
__device__ float g_fr[ROWS*C];
__device__ float g_fl2[ROWS*C];
__device__ float g_fr2[ROWS*C];
__device__ float g_q[ROWS*C];
__device__ float g_kv[ROWS*2*C];
__device__ float g_vo[ROWS*C];
__device__ float g_qr[D2*C];
__device__ float g_kr[D2*C];
__device__ float g_attn[(size_t)NB*NE*W*W];   // raw scores, 268 MB

// ---------------- reorder in: (bs,c,hn,w) -> X[i][j][cc], j=h*2+b ----------------
__global__ void k_reorder_in(const float* __restrict__ in, float* __restrict__ out) {
    __shared__ float sm[32][33];
    int itile = blockIdx.x*32, cctile = blockIdx.y*32, hb = blockIdx.z;
    int h = hb >> 1, b = hb & 1, j = h*2 + b;
    int tx = threadIdx.x, ty = threadIdx.y;
    #pragma unroll
    for (int r = 0; r < 32; r += 8) {
        int cc = cctile + r + ty;
        sm[r+ty][tx] = in[ ((b*C + cc)*HN + h)*W + itile + tx ];
    }
    __syncthreads();
    #pragma unroll
    for (int r = 0; r < 32; r += 8) {
        int i = itile + r + ty;
        out[ (i*NB + j)*C + cctile + tx ] = sm[tx][r+ty];
    }
}

// ---------------- reorder out: X[i][j][cc] -> (bs,c,hn,w) ----------------
__global__ void k_reorder_out(const float* __restrict__ X, float* __restrict__ out) {
    __shared__ float sm[32][33];
    int itile = blockIdx.x*32, cctile = blockIdx.y*32, hb = blockIdx.z;
    int h = hb >> 1, b = hb & 1, j = h*2 + b;
    int tx = threadIdx.x, ty = threadIdx.y;
    #pragma unroll
    for (int r = 0; r < 32; r += 8) {
        int i = itile + r + ty;
        sm[r+ty][tx] = X[ (i*NB + j)*C + cctile + tx ];
    }
    __syncthreads();
    #pragma unroll
    for (int r = 0; r < 32; r += 8) {
        int cc = cctile + r + ty;
        out[ ((b*C + cc)*HN + h)*W + itile + tx ] = sm[tx][r+ty];
    }
}

// ---------------- layernorm over last dim (C=128), one row per block ----------------
__global__ void k_layernorm(const float* __restrict__ X, float* __restrict__ Y,
                            const float* __restrict__ g, const float* __restrict__ b) {
    int row = blockIdx.x;
    int t = threadIdx.x;          // 128
    float x = X[row*C + t];
    __shared__ float red[4];
    float s = x;
    #pragma unroll
    for (int o = 16; o; o >>= 1) s += __shfl_xor_sync(0xffffffffu, s, o);
    if ((t & 31) == 0) red[t >> 5] = s;
    __syncthreads();
    float mean = (red[0]+red[1]+red[2]+red[3]) * (1.0f/C);
    float d = x - mean;
    float s2 = d*d;
    #pragma unroll
    for (int o = 16; o; o >>= 1) s2 += __shfl_xor_sync(0xffffffffu, s2, o);
    __syncthreads();
    if ((t & 31) == 0) red[t >> 5] = s2;
    __syncthreads();
    float var = (red[0]+red[1]+red[2]+red[3]) * (1.0f/C);
    Y[row*C + t] = d * rsqrtf(var + 1e-5f) * g[t] + b[t];
}

// ---------------- SGEMM v2: tile 64(M)x128(N), K chunked by 32, LDS.128 fragments ----
__global__ __launch_bounds__(256, 4)
void k_gemm(const float* __restrict__ A, const float* __restrict__ Wr,
            const float* __restrict__ bias, const float* __restrict__ res,
            float* __restrict__ Cout, int M, float scale, int ldc) {
    __shared__ float As[32*68];    // [k][m]
    __shared__ float Bs[32*132];   // [k][n]
    int m0 = blockIdx.x*64, n0 = blockIdx.y*128;
    int tid = threadIdx.x;
    int tx = tid & 15, ty = tid >> 4;
    float acc[4][8] = {};

    for (int kc = 0; kc < 128; kc += 32) {
        __syncthreads();
        #pragma unroll
        for (int rep = 0; rep < 2; rep++) {
            int f4 = tid + rep*256;
            int m = f4 >> 3, k4 = f4 & 7;
            int gm = m0 + m;
            float4 v = (gm < M) ? *(const float4*)&A[(size_t)gm*128 + kc + k4*4]
                                : make_float4(0.f,0.f,0.f,0.f);
            As[(4*k4+0)*68 + m] = v.x;
            As[(4*k4+1)*68 + m] = v.y;
            As[(4*k4+2)*68 + m] = v.z;
            As[(4*k4+3)*68 + m] = v.w;
        }
        #pragma unroll
        for (int rep = 0; rep < 4; rep++) {
            int f4 = tid + rep*256;
            int n = f4 >> 3, k4 = f4 & 7;
            float4 v = *(const float4*)&Wr[(size_t)(n0+n)*128 + kc + k4*4];
            Bs[(4*k4+0)*132 + n] = v.x;
            Bs[(4*k4+1)*132 + n] = v.y;
            Bs[(4*k4+2)*132 + n] = v.z;
            Bs[(4*k4+3)*132 + n] = v.w;
        }
        __syncthreads();
        #pragma unroll
        for (int kk = 0; kk < 32; kk++) {
            float4 a  = *(float4*)&As[kk*68 + 4*ty];
            float4 b0 = *(float4*)&Bs[kk*132 + 4*tx];
            float4 b1 = *(float4*)&Bs[kk*132 + 64 + 4*tx];
            float av[4] = {a.x, a.y, a.z, a.w};
            float bv[8] = {b0.x, b0.y, b0.z, b0.w, b1.x, b1.y, b1.z, b1.w};
            #pragma unroll
            for (int r = 0; r < 4; r++)
                #pragma unroll
                for (int c = 0; c < 8; c++) acc[r][c] += av[r]*bv[c];
        }
    }

    float4 bi0 = *(const float4*)&bias[n0 + 4*tx];
    float4 bi1 = *(const float4*)&bias[n0 + 64 + 4*tx];
    float bb[8] = {bi0.x, bi0.y, bi0.z, bi0.w, bi1.x, bi1.y, bi1.z, bi1.w};
    #pragma unroll
    for (int r = 0; r < 4; r++) {
        int gm = m0 + 4*ty + r;
        if (gm >= M) continue;
        float o[8];
        #pragma unroll
        for (int c = 0; c < 8; c++) o[c] = scale * (acc[r][c] + bb[c]);
        size_t base = (size_t)gm*ldc + n0;
        if (res) {
            float4 r0 = *(const float4*)&res[base + 4*tx];
            float4 r1 = *(const float4*)&res[base + 64 + 4*tx];
            o[0]+=r0.x; o[1]+=r0.y; o[2]+=r0.z; o[3]+=r0.w;
            o[4]+=r1.x; o[5]+=r1.y; o[6]+=r1.z; o[7]+=r1.w;
        }
        *(float4*)&Cout[base + 4*tx]      = make_float4(o[0],o[1],o[2],o[3]);
        *(float4*)&Cout[base + 64 + 4*tx] = make_float4(o[4],o[5],o[6],o[7]);
    }
}

// ---------------- scores: attn[n,e,i,v] = q·k + q·kr[d] + qr[d]·k, d = 255+sgn*(i-v) ----
__global__ __launch_bounds__(256, 3)
void k_scores(const float* __restrict__ q, const float* __restrict__ kv,
              const float* __restrict__ qr, const float* __restrict__ kr,
              float* __restrict__ attn, int sgn) {
    __shared__ float Qs[64*17];
    __shared__ float Ks[128*17];
    __shared__ float QRs[192*17];
    __shared__ float KRs[192*17];
    int i0 = (blockIdx.x >> 1) * 64;
    int v0 = (blockIdx.x & 1) * 128;
    int e = blockIdx.y, n = blockIdx.z;
    int tid = threadIdx.x;
    int dmin = (sgn > 0) ? (128 + i0 - v0) : (192 - i0 + v0);
    for (int idx = tid; idx < 64*16; idx += 256) {
        int r = idx >> 4, cc = idx & 15;
        Qs[r*17+cc] = q[(size_t)((i0+r)*NB + n)*C + e*16 + cc];
    }
    for (int idx = tid; idx < 128*16; idx += 256) {
        int r = idx >> 4, cc = idx & 15;
        Ks[r*17+cc] = kv[(size_t)((v0+r)*NB + n)*(2*C) + e*16 + cc];
    }
    for (int idx = tid; idx < 192*16; idx += 256) {
        int r = idx >> 4, cc = idx & 15;
        QRs[r*17+cc] = qr[(dmin+r)*C + e*16 + cc];
        KRs[r*17+cc] = kr[(dmin+r)*C + e*16 + cc];
    }
    __syncthreads();
    int ty = tid & 15, tx = tid >> 4;
    int ib = ty*4, vb = tx*8;
    int dbase = (sgn > 0) ? (127 + ib - vb) : (63 - ib + vb);
    int doff[11];
    #pragma unroll
    for (int k = 0; k < 11; k++) doff[k] = (dbase + sgn*(k - 7))*17;
    float acc[4][8] = {};
    #pragma unroll 2
    for (int cc = 0; cc < 16; cc++) {
        float qa[4], ka[8], qrl[11], krl[11];
        #pragma unroll
        for (int r = 0; r < 4; r++) qa[r] = Qs[(ib+r)*17 + cc];
        #pragma unroll
        for (int r = 0; r < 8; r++) ka[r] = Ks[(vb+r)*17 + cc];
        #pragma unroll
        for (int k = 0; k < 11; k++) { qrl[k] = QRs[doff[k] + cc]; krl[k] = KRs[doff[k] + cc]; }
        #pragma unroll
        for (int ri = 0; ri < 4; ri++)
            #pragma unroll
            for (int rv = 0; rv < 8; rv++) {
                int k = ri - rv + 7;
                acc[ri][rv] += qa[ri]*(ka[rv] + krl[k]) + qrl[k]*ka[rv];
            }
    }
    #pragma unroll
    for (int ri = 0; ri < 4; ri++) {
        int i = i0 + ib + ri;
        float4* dst = (float4*)&attn[ ((size_t)(n*NE + e)*W + i)*W + v0 + vb ];
        dst[0] = make_float4(acc[ri][0], acc[ri][1], acc[ri][2], acc[ri][3]);
        dst[1] = make_float4(acc[ri][4], acc[ri][5], acc[ri][6], acc[ri][7]);
    }
}

// ---------------- raw[n,i,v] = sum_e scores = full-128-dim q·k + q·kr[d] + qr[d]·k ----
// heads partition channels, so the head-sum collapses to full-dim dots. sgn=+1 (MHA2).
__global__ __launch_bounds__(256, 3)
void k_raw(const float* __restrict__ q, const float* __restrict__ kv,
           const float* __restrict__ qr, const float* __restrict__ kr,
           float* __restrict__ rawout) {
    __shared__ float Qs[64*17];
    __shared__ float Ks[128*17];
    __shared__ float QRs[192*17];
    __shared__ float KRs[192*17];
    int i0 = (blockIdx.x >> 1) * 64;
    int v0 = (blockIdx.x & 1) * 128;
    int n = blockIdx.y;
    int tid = threadIdx.x;
    int dmin = 128 + i0 - v0;
    int ty = tid & 15, tx = tid >> 4;
    int ib = ty*4, vb = tx*8;
    int dbase = 127 + ib - vb;
    int doff[11];
    #pragma unroll
    for (int k = 0; k < 11; k++) doff[k] = (dbase + (k - 7))*17;
    float acc[4][8] = {};

    for (int ch = 0; ch < 8; ch++) {             // cc chunks of 16 over full C=128
        __syncthreads();
        for (int idx = tid; idx < 64*16; idx += 256) {
            int r = idx >> 4, cc = idx & 15;
            Qs[r*17+cc] = q[(size_t)((i0+r)*NB + n)*C + ch*16 + cc];
        }
        for (int idx = tid; idx < 128*16; idx += 256) {
            int r = idx >> 4, cc = idx & 15;
            Ks[r*17+cc] = kv[(size_t)((v0+r)*NB + n)*(2*C) + ch*16 + cc];
        }
        for (int idx = tid; idx < 192*16; idx += 256) {
            int r = idx >> 4, cc = idx & 15;
            QRs[r*17+cc] = qr[(dmin+r)*C + ch*16 + cc];
            KRs[r*17+cc] = kr[(dmin+r)*C + ch*16 + cc];
        }
        __syncthreads();
        #pragma unroll 2
        for (int cc = 0; cc < 16; cc++) {
            float qa[4], ka[8], qrl[11], krl[11];
            #pragma unroll
            for (int r = 0; r < 4; r++) qa[r] = Qs[(ib+r)*17 + cc];
            #pragma unroll
            for (int r = 0; r < 8; r++) ka[r] = Ks[(vb+r)*17 + cc];
            #pragma unroll
            for (int k = 0; k < 11; k++) { qrl[k] = QRs[doff[k] + cc]; krl[k] = KRs[doff[k] + cc]; }
            #pragma unroll
            for (int ri = 0; ri < 4; ri++)
                #pragma unroll
                for (int rv = 0; rv < 8; rv++) {
                    int k = ri - rv + 7;
                    acc[ri][rv] += qa[ri]*(ka[rv] + krl[k]) + qrl[k]*ka[rv];
                }
        }
    }
    int b = n & 1, h = n >> 1;
    #pragma unroll
    for (int ri = 0; ri < 4; ri++) {
        int i = i0 + ib + ri;
        float4* dst = (float4*)&rawout[ ((size_t)(b*HN + h)*W + i)*W + v0 + vb ];
        dst[0] = make_float4(acc[ri][0], acc[ri][1], acc[ri][2], acc[ri][3]);
        dst[1] = make_float4(acc[ri][4], acc[ri][5], acc[ri][6], acc[ri][7]);
    }
}

// ---------------- fused online-softmax + AV over raw scores ----------------
// vo[i,n,e*16+cc] = sum_v softmax_v(S[n,e,i,:]) * V[v,n,e*16+cc]
__global__ void k_av(const float* __restrict__ attn, const float* __restrict__ kv,
                     float* __restrict__ vo) {
    __shared__ float Ps[256][33];
    __shared__ float Vs[32][17];
    int e = blockIdx.x, n = blockIdx.y;
    int t = threadIdx.x;     // 128: rows t and t+128
    float acc[2][16] = {};
    float m0 = -1e30f, m1 = -1e30f, s0 = 0.f, s1 = 0.f;
    const float* P = attn + (size_t)(n*NE + e)*W*W;
    for (int v0 = 0; v0 < W; v0 += 32) {
        __syncthreads();
        #pragma unroll
        for (int k = 0; k < 64; k++) {
            int idx = t + k*128;
            int ii = idx >> 5, vv = idx & 31;
            Ps[ii][vv] = P[(size_t)ii*W + v0 + vv];
        }
        #pragma unroll
        for (int k = 0; k < 4; k++) {
            int idx = t + k*128;
            int vv = idx >> 4, cc = idx & 15;
            Vs[vv][cc] = kv[(size_t)((v0+vv)*NB + n)*(2*C) + C + e*16 + cc];
        }
        __syncthreads();
        // chunk maxima
        float cm0 = -1e30f, cm1 = -1e30f;
        #pragma unroll 8
        for (int vv = 0; vv < 32; vv++) {
            cm0 = fmaxf(cm0, Ps[t][vv]);
            cm1 = fmaxf(cm1, Ps[t+128][vv]);
        }
        // rescale running state
        if (cm0 > m0) {
            float c = __expf(m0 - cm0);
            s0 *= c;
            #pragma unroll
            for (int cc = 0; cc < 16; cc++) acc[0][cc] *= c;
            m0 = cm0;
        }
        if (cm1 > m1) {
            float c = __expf(m1 - cm1);
            s1 *= c;
            #pragma unroll
            for (int cc = 0; cc < 16; cc++) acc[1][cc] *= c;
            m1 = cm1;
        }
        #pragma unroll 4
        for (int vv = 0; vv < 32; vv++) {
            float p0 = __expf(Ps[t][vv] - m0);
            float p1 = __expf(Ps[t+128][vv] - m1);
            s0 += p0; s1 += p1;
            #pragma unroll
            for (int cc = 0; cc < 16; cc++) {
                float vx = Vs[vv][cc];
                acc[0][cc] += p0*vx;
                acc[1][cc] += p1*vx;
            }
        }
    }
    float inv0 = 1.0f/s0, inv1 = 1.0f/s1;
    {
        float4* dst = (float4*)&vo[(size_t)((size_t)(t)*NB + n)*C + e*16];
        dst[0] = make_float4(acc[0][0]*inv0, acc[0][1]*inv0, acc[0][2]*inv0, acc[0][3]*inv0);
        dst[1] = make_float4(acc[0][4]*inv0, acc[0][5]*inv0, acc[0][6]*inv0, acc[0][7]*inv0);
        dst[2] = make_float4(acc[0][8]*inv0, acc[0][9]*inv0, acc[0][10]*inv0, acc[0][11]*inv0);
        dst[3] = make_float4(acc[0][12]*inv0, acc[0][13]*inv0, acc[0][14]*inv0, acc[0][15]*inv0);
    }
    {
        float4* dst = (float4*)&vo[(size_t)((size_t)(t+128)*NB + n)*C + e*16];
        dst[0] = make_float4(acc[1][0]*inv1, acc[1][1]*inv1, acc[1][2]*inv1, acc[1][3]*inv1);
        dst[1] = make_float4(acc[1][4]*inv1, acc[1][5]*inv1, acc[1][6]*inv1, acc[1][7]*inv1);
        dst[2] = make_float4(acc[1][8]*inv1, acc[1][9]*inv1, acc[1][10]*inv1, acc[1][11]*inv1);
        dst[3] = make_float4(acc[1][12]*inv1, acc[1][13]*inv1, acc[1][14]*inv1, acc[1][15]*inv1);
    }
}

// ---------------- host ----------------
extern "C" void kernel_launch(void* const* d_in, const int* in_sizes, int n_in,
                              void* d_out, int out_size) {
    const float* feat_left  = (const float*)d_in[0];
    const float* feat_right = (const float*)d_in[1];
    const float* pos        = (const float*)d_in[2];
    // d_in[3] pos_indexes: analytic d = 255 +/- (i-v) used instead
    const float* Wqkv = (const float*)d_in[4];
    const float* bqkv = (const float*)d_in[5];
    const float* Wo   = (const float*)d_in[6];
    const float* bo   = (const float*)d_in[7];
    const float* g1   = (const float*)d_in[8];
    const float* b1   = (const float*)d_in[9];
    const float* g2   = (const float*)d_in[10];
    const float* b2   = (const float*)d_in[11];
    float* out = (float*)d_out;

    float *fl,*fr,*fl2,*fr2,*q,*kv,*vo,*qr,*kr,*attn;
    cudaGetSymbolAddress((void**)&fl,   g_fl);
    cudaGetSymbolAddress((void**)&fr,   g_fr);
    cudaGetSymbolAddress((void**)&fl2,  g_fl2);
    cudaGetSymbolAddress((void**)&fr2,  g_fr2);
    cudaGetSymbolAddress((void**)&q,    g_q);
    cudaGetSymbolAddress((void**)&kv,   g_kv);
    cudaGetSymbolAddress((void**)&vo,   g_vo);
    cudaGetSymbolAddress((void**)&qr,   g_qr);
    cudaGetSymbolAddress((void**)&kr,   g_kr);
    cudaGetSymbolAddress((void**)&attn, g_attn);

    dim3 bt(32, 8);
    dim3 gt(8, 4, 128);

    // to_seq + LN(g1,b1)
    k_reorder_in<<<gt, bt>>>(feat_left,  fl);
    k_reorder_in<<<gt, bt>>>(feat_right, fr);
    k_layernorm<<<ROWS, 128>>>(fl, fl2, g1, b1);
    k_layernorm<<<ROWS, 128>>>(fr, fr2, g1, b1);

    // positional tables: qr = 0.25*(pos@Wq^T+bq), kr = pos@Wk^T+bk
    k_gemm<<<dim3(8,1), 256>>>(pos, Wqkv,           bqkv,     nullptr, qr, D2, 0.25f, 128);
    k_gemm<<<dim3(8,1), 256>>>(pos, Wqkv + 128*128, bqkv+128, nullptr, kr, D2, 1.0f,  128);

    // ---- MHA 1: q from fr2, kv from fl2, flipped pos => d = 255 - (i - v) ----
    k_gemm<<<dim3(512,1), 256>>>(fr2, Wqkv,           bqkv,     nullptr, q,  ROWS, 0.25f, 128);
    k_gemm<<<dim3(512,2), 256>>>(fl2, Wqkv + 128*128, bqkv+128, nullptr, kv, ROWS, 1.0f,  256);
    k_scores<<<dim3(8, NE, NB), 256>>>(q, kv, qr, kr, attn, -1);
    k_av<<<dim3(NE, NB), 128>>>(attn, kv, vo);
    k_gemm<<<dim3(512,1), 256>>>(vo, Wo, bo, fr, fr, ROWS, 1.0f, 128);  // fr += upd_r

    // fr2 <- ln(fr, g2, b2)
    k_layernorm<<<ROWS, 128>>>(fr, fr2, g2, b2);

    // ---- MHA 2: q from fl2, kv from fr2, d = 255 + (i - v), raw analytic -> output ----
    k_gemm<<<dim3(512,1), 256>>>(fl2, Wqkv,           bqkv,     nullptr, q,  ROWS, 0.25f, 128);
    k_gemm<<<dim3(512,2), 256>>>(fr2, Wqkv + 128*128, bqkv+128, nullptr, kv, ROWS, 1.0f,  256);
    k_scores<<<dim3(8, NE, NB), 256>>>(q, kv, qr, kr, attn, +1);
    k_raw<<<dim3(8, NB), 256>>>(q, kv, qr, kr, out + 8388608);
    k_av<<<dim3(NE, NB), 128>>>(attn, kv, vo);
    k_gemm<<<dim3(512,1), 256>>>(vo, Wo, bo, fl, fl, ROWS, 1.0f, 128);  // fl += upd_l

    // from_seq
    k_reorder_out<<<gt, bt>>>(fl, out);
    k_reorder_out<<<gt, bt>>>(fr, out + 4194304);
}